// round 15
// baseline (speedup 1.0000x reference)
#include <cuda_runtime.h>
#include <cuda_bf16.h>

// f  : (B=32, H=512, W=512) f32
// K  : (5, 5, H, W)         f32  -> bf16x2 taps in regs (shared over batch)
// dt : (B,)                 f32
// out = relu(f + conv5x5_perpixel(f) * dt[b]),  center f kept exact fp32.
//
// R14: R13 (best, 24.7us) + epilogue-latency removal:
//  - center fp32 LDG.128s + dt4 hoisted BEFORE the compute loop (hide ~300+
//    cycles of L2 latency under the HFMA2 work)
//  - __stcs streaming stores for out (keep K/f resident in L2 for the
//    second grid.z wave)

#define B_     32
#define H_     512
#define W_     512
#define HW_    (H_ * W_)
#define KS     5
#define RAD    2
#define TW     32                  // tile width px  (8 thr x 4 px)
#define TH     16                  // tile height px
#define TILE_W 36
#define TILE_H 20
#define SSTRB  192                 // bytes per smem tile row (96 bf16 slots)
#define PLANEB (TILE_H * SSTRB)    // 3840 B per batch plane
#define NB     4
#define BSPLIT 2                   // batch split over grid.z
#define NPASS  (B_ / BSPLIT / NB)  // 4
#define NTHR   128

union U32B2 { unsigned u; __nv_bfloat162 b; };
__device__ __forceinline__ __nv_bfloat162 u2b(unsigned u) { U32B2 c; c.u = u; return c.b; }
__device__ __forceinline__ unsigned b2u(__nv_bfloat162 b) { U32B2 c; c.b = b; return c.u; }

__global__ __launch_bounds__(NTHR, 4)
void op2d_kernel(const float* __restrict__ f,
                 const float* __restrict__ K,
                 const float* __restrict__ dt,
                 float* __restrict__ out)
{
    __shared__ __align__(16) unsigned char sbuf[2][NB * PLANEB];   // 2x15360 B

    const int tid = threadIdx.x;        // 0..127
    const int txc = tid & 7;            // 4 px each
    const int ty  = tid >> 3;           // 0..15
    const int bx  = blockIdx.x * TW;
    const int by  = blockIdx.y * TH;
    const int x0  = bx + txc * 4;
    const int y   = by + ty;
    const int pix = y * W_ + x0;        // 16B-aligned
    const int bb0 = blockIdx.z * (B_ / BSPLIT);   // first batch for this CTA

    // ---- 25 taps x 4 px, packed as 2x bf16x2 per tap (50 regs)
    __nv_bfloat162 kvA[25], kvB[25];
#pragma unroll
    for (int t = 0; t < 25; ++t) {
        const float4 k4 = __ldg((const float4*)(K + t * HW_ + pix));
        kvA[t] = __floats2bfloat162_rn(k4.x, k4.y);   // px0, px1
        kvB[t] = __floats2bfloat162_rn(k4.z, k4.w);   // px2, px3
    }

    // ---- staging map: 126 threads cover 18 col-pairs x rows {r0, r0+7, r0+14}
    const int  c      = tid % 18;                 // pair column (sx = 2c, 2c+1)
    const int  r0     = tid / 18;                 // 0..7
    const bool st_act = (tid < 126);
    const int  gx0    = bx - 2 + 2 * c;           // even -> float2-aligned
    const bool vx     = (unsigned)gx0 < (unsigned)W_;

    bool vv[3]; bool su[3]; const float* gp[3]; unsigned sp[3];
#pragma unroll
    for (int it = 0; it < 3; ++it) {
        const int r  = r0 + 7 * it;
        const int gy = by - 2 + r;
        su[it] = st_act && (r < TILE_H);
        vv[it] = su[it] && vx && ((unsigned)gy < (unsigned)H_);
        gp[it] = f + (vv[it] ? (bb0 * HW_ + gy * W_ + gx0) : 0);
        sp[it] = (unsigned)(r * SSTRB + c * 4);
    }

    const int rbyte0 = ty * SSTRB + txc * 8;      // window byte base

    // ---- prologue: stage pass 0 into buffer 0
    unsigned pre[NB * 3];
#pragma unroll
    for (int b = 0; b < NB; ++b)
#pragma unroll
        for (int it = 0; it < 3; ++it) {
            float2 v = vv[it] ? *(const float2*)(gp[it] + b * HW_)
                              : make_float2(0.0f, 0.0f);
            pre[b * 3 + it] = b2u(__floats2bfloat162_rn(v.x, v.y));
        }
#pragma unroll
    for (int b = 0; b < NB; ++b)
#pragma unroll
        for (int it = 0; it < 3; ++it)
            if (su[it])
                *(unsigned*)(sbuf[0] + b * PLANEB + sp[it]) = pre[b * 3 + it];
    __syncthreads();

    int cur = 0;

    for (int pass = 0; pass < NPASS; ++pass) {
        const int b0  = bb0 + pass * NB;
        const int nxt = cur ^ 1;

        // -- prefetch pass+1 tiles (LDG latency hidden under compute)
        if (pass + 1 < NPASS) {
            const long poff = (long)(pass + 1) * NB * HW_;
#pragma unroll
            for (int b = 0; b < NB; ++b)
#pragma unroll
                for (int it = 0; it < 3; ++it) {
                    float2 v = vv[it]
                        ? *(const float2*)(gp[it] + poff + b * HW_)
                        : make_float2(0.0f, 0.0f);
                    pre[b * 3 + it] = b2u(__floats2bfloat162_rn(v.x, v.y));
                }
        }

        // -- hoisted epilogue operands: center fp32 + dt (land under compute)
        float4 c4[NB];
#pragma unroll
        for (int b = 0; b < NB; ++b)
            c4[b] = __ldg((const float4*)(f + (b0 + b) * HW_ + pix));
        const float4 dt4 = __ldg((const float4*)(dt + b0));
        const float dts[4] = { dt4.x, dt4.y, dt4.z, dt4.w };

        // -- 5x5 conv, bf16 HFMA2: per kernel row i, batch all 8 LDS.64
        //    (4 planes x lo/hi) back-to-back, then consume.
        __nv_bfloat162 accA[NB], accB[NB];
        const __nv_bfloat162 z2 = __floats2bfloat162_rn(0.0f, 0.0f);
#pragma unroll
        for (int b = 0; b < NB; ++b) { accA[b] = z2; accB[b] = z2; }

        const unsigned char* prow = sbuf[cur] + rbyte0;
#pragma unroll
        for (int i = 0; i < KS; ++i) {
            uint2 lo[NB], hi[NB];
#pragma unroll
            for (int b = 0; b < NB; ++b) {
                const unsigned char* p = prow + b * PLANEB;
                lo[b] = *(const uint2*)(p);       // (t0,t1),(t2,t3)
                hi[b] = *(const uint2*)(p + 8);   // (t4,t5),(t6,t7)
            }
#pragma unroll
            for (int b = 0; b < NB; ++b) {
                const unsigned w01 = lo[b].x, w23 = lo[b].y;
                const unsigned w45 = hi[b].x, w67 = hi[b].y;
                const unsigned w12 = __byte_perm(w01, w23, 0x5432);
                const unsigned w34 = __byte_perm(w23, w45, 0x5432);
                const unsigned w56 = __byte_perm(w45, w67, 0x5432);

                accA[b] = __hfma2(kvA[i*5+0], u2b(w01), accA[b]);
                accA[b] = __hfma2(kvA[i*5+1], u2b(w12), accA[b]);
                accA[b] = __hfma2(kvA[i*5+2], u2b(w23), accA[b]);
                accA[b] = __hfma2(kvA[i*5+3], u2b(w34), accA[b]);
                accA[b] = __hfma2(kvA[i*5+4], u2b(w45), accA[b]);

                accB[b] = __hfma2(kvB[i*5+0], u2b(w23), accB[b]);
                accB[b] = __hfma2(kvB[i*5+1], u2b(w34), accB[b]);
                accB[b] = __hfma2(kvB[i*5+2], u2b(w45), accB[b]);
                accB[b] = __hfma2(kvB[i*5+3], u2b(w56), accB[b]);
                accB[b] = __hfma2(kvB[i*5+4], u2b(w67), accB[b]);
            }
            prow += SSTRB;
        }

        // -- epilogue: out = relu(fc + acc*dt), streaming float4 store
#pragma unroll
        for (int b = 0; b < NB; ++b) {
            const unsigned ua = b2u(accA[b]);
            const unsigned ub = b2u(accB[b]);
            const float a0 = __uint_as_float(ua << 16);
            const float a1 = __uint_as_float(ua & 0xFFFF0000u);
            const float a2 = __uint_as_float(ub << 16);
            const float a3 = __uint_as_float(ub & 0xFFFF0000u);
            const float dtb = dts[b];
            float4 o;
            o.x = fmaxf(fmaf(a0, dtb, c4[b].x), 0.0f);
            o.y = fmaxf(fmaf(a1, dtb, c4[b].y), 0.0f);
            o.z = fmaxf(fmaf(a2, dtb, c4[b].z), 0.0f);
            o.w = fmaxf(fmaf(a3, dtb, c4[b].w), 0.0f);
            __stcs((float4*)(out + (b0 + b) * HW_ + pix), o);
        }

        // -- commit prefetched tiles into the other buffer, single barrier
        if (pass + 1 < NPASS) {
#pragma unroll
            for (int b = 0; b < NB; ++b)
#pragma unroll
                for (int it = 0; it < 3; ++it)
                    if (su[it])
                        *(unsigned*)(sbuf[nxt] + b * PLANEB + sp[it]) = pre[b * 3 + it];
        }
        __syncthreads();
        cur = nxt;
    }
}

extern "C" void kernel_launch(void* const* d_in, const int* in_sizes, int n_in,
                              void* d_out, int out_size)
{
    const float* f  = (const float*)d_in[0];
    const float* K  = (const float*)d_in[1];
    const float* dt = (const float*)d_in[2];
    float* out = (float*)d_out;

    dim3 grid(W_ / TW, H_ / TH, BSPLIT);   // 16 x 32 x 2 = 1024 CTAs
    dim3 block(NTHR);
    op2d_kernel<<<grid, block>>>(f, K, dt, out);
}

// round 16
// speedup vs baseline: 1.4125x; 1.4125x over previous
#include <cuda_runtime.h>
#include <cuda_bf16.h>

// f  : (B=32, H=512, W=512) f32
// K  : (5, 5, H, W)         f32  -> bf16x2 taps in regs (shared over batch)
// dt : (B,)                 f32
// out = relu(f + conv5x5_perpixel(f) * dt[b]),  center f kept exact fp32.
//
// R15: R13 (measured best 24.7us) restored VERBATIM -- c4/dt loads stay in
// the epilogue (no live regs across the compute loop; R14 proved a 16-reg
// hoist spills) -- with exactly ONE delta: __stcs streaming stores for out
// (no extra live state; isolates the store-policy variable).

#define B_     32
#define H_     512
#define W_     512
#define HW_    (H_ * W_)
#define KS     5
#define RAD    2
#define TW     32                  // tile width px  (8 thr x 4 px)
#define TH     16                  // tile height px
#define TILE_W 36
#define TILE_H 20
#define SSTRB  192                 // bytes per smem tile row (96 bf16 slots)
#define PLANEB (TILE_H * SSTRB)    // 3840 B per batch plane
#define NB     4
#define BSPLIT 2                   // batch split over grid.z
#define NPASS  (B_ / BSPLIT / NB)  // 4
#define NTHR   128

union U32B2 { unsigned u; __nv_bfloat162 b; };
__device__ __forceinline__ __nv_bfloat162 u2b(unsigned u) { U32B2 c; c.u = u; return c.b; }
__device__ __forceinline__ unsigned b2u(__nv_bfloat162 b) { U32B2 c; c.b = b; return c.u; }

__global__ __launch_bounds__(NTHR, 4)
void op2d_kernel(const float* __restrict__ f,
                 const float* __restrict__ K,
                 const float* __restrict__ dt,
                 float* __restrict__ out)
{
    __shared__ __align__(16) unsigned char sbuf[2][NB * PLANEB];   // 2x15360 B

    const int tid = threadIdx.x;        // 0..127
    const int txc = tid & 7;            // 4 px each
    const int ty  = tid >> 3;           // 0..15
    const int bx  = blockIdx.x * TW;
    const int by  = blockIdx.y * TH;
    const int x0  = bx + txc * 4;
    const int y   = by + ty;
    const int pix = y * W_ + x0;        // 16B-aligned
    const int bb0 = blockIdx.z * (B_ / BSPLIT);   // first batch for this CTA

    // ---- 25 taps x 4 px, packed as 2x bf16x2 per tap (50 regs)
    __nv_bfloat162 kvA[25], kvB[25];
#pragma unroll
    for (int t = 0; t < 25; ++t) {
        const float4 k4 = __ldg((const float4*)(K + t * HW_ + pix));
        kvA[t] = __floats2bfloat162_rn(k4.x, k4.y);   // px0, px1
        kvB[t] = __floats2bfloat162_rn(k4.z, k4.w);   // px2, px3
    }

    // ---- staging map: 126 threads cover 18 col-pairs x rows {r0, r0+7, r0+14}
    const int  c      = tid % 18;                 // pair column (sx = 2c, 2c+1)
    const int  r0     = tid / 18;                 // 0..7
    const bool st_act = (tid < 126);
    const int  gx0    = bx - 2 + 2 * c;           // even -> float2-aligned
    const bool vx     = (unsigned)gx0 < (unsigned)W_;

    bool vv[3]; bool su[3]; const float* gp[3]; unsigned sp[3];
#pragma unroll
    for (int it = 0; it < 3; ++it) {
        const int r  = r0 + 7 * it;
        const int gy = by - 2 + r;
        su[it] = st_act && (r < TILE_H);
        vv[it] = su[it] && vx && ((unsigned)gy < (unsigned)H_);
        gp[it] = f + (vv[it] ? (bb0 * HW_ + gy * W_ + gx0) : 0);
        sp[it] = (unsigned)(r * SSTRB + c * 4);
    }

    const int rbyte0 = ty * SSTRB + txc * 8;      // window byte base

    // ---- prologue: stage pass 0 into buffer 0
    unsigned pre[NB * 3];
#pragma unroll
    for (int b = 0; b < NB; ++b)
#pragma unroll
        for (int it = 0; it < 3; ++it) {
            float2 v = vv[it] ? *(const float2*)(gp[it] + b * HW_)
                              : make_float2(0.0f, 0.0f);
            pre[b * 3 + it] = b2u(__floats2bfloat162_rn(v.x, v.y));
        }
#pragma unroll
    for (int b = 0; b < NB; ++b)
#pragma unroll
        for (int it = 0; it < 3; ++it)
            if (su[it])
                *(unsigned*)(sbuf[0] + b * PLANEB + sp[it]) = pre[b * 3 + it];
    __syncthreads();

    int cur = 0;

    for (int pass = 0; pass < NPASS; ++pass) {
        const int b0  = bb0 + pass * NB;
        const int nxt = cur ^ 1;

        // -- prefetch pass+1 (LDG latency hidden under this pass's compute)
        if (pass + 1 < NPASS) {
            const long poff = (long)(pass + 1) * NB * HW_;
#pragma unroll
            for (int b = 0; b < NB; ++b)
#pragma unroll
                for (int it = 0; it < 3; ++it) {
                    float2 v = vv[it]
                        ? *(const float2*)(gp[it] + poff + b * HW_)
                        : make_float2(0.0f, 0.0f);
                    pre[b * 3 + it] = b2u(__floats2bfloat162_rn(v.x, v.y));
                }
        }

        // -- 5x5 conv, bf16 HFMA2: per kernel row i, batch all 8 LDS.64
        //    (4 planes x lo/hi) back-to-back, then consume.
        __nv_bfloat162 accA[NB], accB[NB];
        const __nv_bfloat162 z2 = __floats2bfloat162_rn(0.0f, 0.0f);
#pragma unroll
        for (int b = 0; b < NB; ++b) { accA[b] = z2; accB[b] = z2; }

        const unsigned char* prow = sbuf[cur] + rbyte0;
#pragma unroll
        for (int i = 0; i < KS; ++i) {
            uint2 lo[NB], hi[NB];
#pragma unroll
            for (int b = 0; b < NB; ++b) {
                const unsigned char* p = prow + b * PLANEB;
                lo[b] = *(const uint2*)(p);       // (t0,t1),(t2,t3)
                hi[b] = *(const uint2*)(p + 8);   // (t4,t5),(t6,t7)
            }
#pragma unroll
            for (int b = 0; b < NB; ++b) {
                const unsigned w01 = lo[b].x, w23 = lo[b].y;
                const unsigned w45 = hi[b].x, w67 = hi[b].y;
                const unsigned w12 = __byte_perm(w01, w23, 0x5432);
                const unsigned w34 = __byte_perm(w23, w45, 0x5432);
                const unsigned w56 = __byte_perm(w45, w67, 0x5432);

                accA[b] = __hfma2(kvA[i*5+0], u2b(w01), accA[b]);
                accA[b] = __hfma2(kvA[i*5+1], u2b(w12), accA[b]);
                accA[b] = __hfma2(kvA[i*5+2], u2b(w23), accA[b]);
                accA[b] = __hfma2(kvA[i*5+3], u2b(w34), accA[b]);
                accA[b] = __hfma2(kvA[i*5+4], u2b(w45), accA[b]);

                accB[b] = __hfma2(kvB[i*5+0], u2b(w23), accB[b]);
                accB[b] = __hfma2(kvB[i*5+1], u2b(w34), accB[b]);
                accB[b] = __hfma2(kvB[i*5+2], u2b(w45), accB[b]);
                accB[b] = __hfma2(kvB[i*5+3], u2b(w56), accB[b]);
                accB[b] = __hfma2(kvB[i*5+4], u2b(w67), accB[b]);
            }
            prow += SSTRB;
        }

        // -- epilogue: exact fp32 center (L2-hit), out = relu(fc + acc*dt)
        const float4 dt4 = __ldg((const float4*)(dt + b0));
        const float dts[4] = { dt4.x, dt4.y, dt4.z, dt4.w };
#pragma unroll
        for (int b = 0; b < NB; ++b) {
            const float4 c4 = __ldg((const float4*)(f + (b0 + b) * HW_ + pix));
            const unsigned ua = b2u(accA[b]);
            const unsigned ub = b2u(accB[b]);
            const float a0 = __uint_as_float(ua << 16);
            const float a1 = __uint_as_float(ua & 0xFFFF0000u);
            const float a2 = __uint_as_float(ub << 16);
            const float a3 = __uint_as_float(ub & 0xFFFF0000u);
            const float dtb = dts[b];
            float4 o;
            o.x = fmaxf(fmaf(a0, dtb, c4.x), 0.0f);
            o.y = fmaxf(fmaf(a1, dtb, c4.y), 0.0f);
            o.z = fmaxf(fmaf(a2, dtb, c4.z), 0.0f);
            o.w = fmaxf(fmaf(a3, dtb, c4.w), 0.0f);
            __stcs((float4*)(out + (b0 + b) * HW_ + pix), o);
        }

        // -- commit prefetched tiles into the other buffer, single barrier
        if (pass + 1 < NPASS) {
#pragma unroll
            for (int b = 0; b < NB; ++b)
#pragma unroll
                for (int it = 0; it < 3; ++it)
                    if (su[it])
                        *(unsigned*)(sbuf[nxt] + b * PLANEB + sp[it]) = pre[b * 3 + it];
        }
        __syncthreads();
        cur = nxt;
    }
}

extern "C" void kernel_launch(void* const* d_in, const int* in_sizes, int n_in,
                              void* d_out, int out_size)
{
    const float* f  = (const float*)d_in[0];
    const float* K  = (const float*)d_in[1];
    const float* dt = (const float*)d_in[2];
    float* out = (float*)d_out;

    dim3 grid(W_ / TW, H_ / TH, BSPLIT);   // 16 x 32 x 2 = 1024 CTAs
    dim3 block(NTHR);
    op2d_kernel<<<grid, block>>>(f, K, dt, out);
}